// round 4
// baseline (speedup 1.0000x reference)
#include <cuda_runtime.h>

// ContrastiveLoss (discriminative loss), fixed shapes:
//   input_:  (4, 32, 512, 512) float32, channel-major
//   target:  (4, 1, 512, 512)  int32, labels in [0, 100)
// Output: scalar float32.

#define BB 4
#define CC 32
#define HW 262144
#define NI 100
#define PITCH 33              // table pitch: bank(l*33+c) = (l+c)%32, conflict-free per row
#define ROWS 103              // 100 real rows + 3 dummy rows for dedup redirect
#define TSZ (ROWS * PITCH)    // 3399 floats = 13.6KB
#define P2 36                 // pass-2 mean pitch (16B aligned rows)
#define DVAR 0.75f
#define REP 4.0f              // 2 * DELTA_DIST

__device__ float g_sum[BB * NI * CC];
__device__ float g_cnt[BB * NI];

// ---------------------------------------------------------------------------
__global__ void k_zero(float* __restrict__ out) {
    int i = blockIdx.x * 256 + threadIdx.x;
    if (i < BB * NI * CC) g_sum[i] = 0.0f;
    if (i < BB * NI)      g_cnt[i] = 0.0f;
    if (i == 0)           out[0]   = 0.0f;
}

// ---------------------------------------------------------------------------
// Branchless 4-pixel RMW into the warp-private table.
// Duplicate labels are merged into the earliest slot; freed slots are
// redirected to dummy rows 100..102 so the 4 addresses are always distinct
// -> always batched (4 LDS, 4 STS, full ILP), never a serialized chain.
// Labels are warp-uniform (smem broadcast), so all control is non-divergent.
__device__ __forceinline__ void rmw4(float* __restrict__ T, int lane,
                                     int l0, int l1, int l2, int l3,
                                     float v0, float v1, float v2, float v3) {
    float c0 = 1.0f, c1 = 1.0f, c2 = 1.0f, c3 = 1.0f;
    if (l1 == l0) { v0 += v1; c0 += c1; v1 = 0.0f; c1 = 0.0f; l1 = NI; }
    if (l2 == l0) { v0 += v2; c0 += c2; v2 = 0.0f; c2 = 0.0f; l2 = NI + 1; }
    else if (l2 == l1) { v1 += v2; c1 += c2; v2 = 0.0f; c2 = 0.0f; l2 = NI + 1; }
    if (l3 == l0) { v0 += v3; c0 += c3; v3 = 0.0f; c3 = 0.0f; l3 = NI + 2; }
    else if (l3 == l1) { v1 += v3; c1 += c3; v3 = 0.0f; c3 = 0.0f; l3 = NI + 2; }
    else if (l3 == l2) { v2 += v3; c2 += c3; v3 = 0.0f; c3 = 0.0f; l3 = NI + 2; }

    const int a0 = l0 * PITCH + lane, a1 = l1 * PITCH + lane;
    const int a2 = l2 * PITCH + lane, a3 = l3 * PITCH + lane;
    const float t0 = T[a0], t1 = T[a1], t2 = T[a2], t3 = T[a3];
    T[a0] = t0 + v0;  T[a1] = t1 + v1;  T[a2] = t2 + v2;  T[a3] = t3 + v3;

    if (lane < 4) {    // counts: 4 lanes, 4 distinct rows (post-dedup)
        const int   ll = (lane == 0) ? l0 : (lane == 1) ? l1 : (lane == 2) ? l2 : l3;
        const float cc = (lane == 0) ? c0 : (lane == 1) ? c1 : (lane == 2) ? c2 : c3;
        T[ll * PITCH + 32] += cc;
    }
}

// ---------------------------------------------------------------------------
// Pass 1: per-label channel sums + counts. Block = 2 warps, each with a
// private 103x33 table. Lane = channel; features come straight from gmem as
// 2x LDG.128 per 8 pixels (32B/lane = full sectors). Grid (256, 4); each
// warp owns 512 contiguous pixels.
__global__ void __launch_bounds__(64) k_pass1(const float* __restrict__ in,
                                              const int* __restrict__ tgt) {
    __shared__ __align__(16) float tab[2][TSZ];   // 27.2 KB
    __shared__ __align__(16) int   lab[2][64];

    const int b    = blockIdx.y;
    const int warp = threadIdx.x >> 5;
    const int lane = threadIdx.x & 31;
    float* T = tab[warp];
    int*   L = lab[warp];

    for (int i = threadIdx.x; i < 2 * TSZ; i += 64) (&tab[0][0])[i] = 0.0f;
    __syncthreads();

    const int*   tb   = tgt + (size_t)b * HW;
    const float* rowc = in + (size_t)b * CC * HW + (size_t)lane * HW;
    const int base = (blockIdx.x * 2 + warp) * 512;

    for (int ch = 0; ch < 8; ++ch) {
        const int p0 = base + ch * 64;
        if (lane < 16) ((int4*)L)[lane] = ((const int4*)(tb + p0))[lane];
        __syncwarp();

#pragma unroll
        for (int g = 0; g < 8; ++g) {
            const int p = p0 + g * 8;
            const float4 A  = *(const float4*)(rowc + p);
            const float4 Bv = *(const float4*)(rowc + p + 4);
            const int4 La = *(const int4*)(L + g * 8);
            const int4 Lb = *(const int4*)(L + g * 8 + 4);
            rmw4(T, lane, La.x, La.y, La.z, La.w, A.x,  A.y,  A.z,  A.w);
            rmw4(T, lane, Lb.x, Lb.y, Lb.z, Lb.w, Bv.x, Bv.y, Bv.z, Bv.w);
        }
        __syncwarp();
    }
    __syncthreads();

    // flush real rows (dummy rows 100..102 discarded)
    for (int l = threadIdx.x; l < NI; l += 64) {
#pragma unroll
        for (int c = 0; c < CC; ++c) {
            const float s = tab[0][l * PITCH + c] + tab[1][l * PITCH + c];
            atomicAdd(&g_sum[(b * NI + l) * CC + c], s);
        }
        atomicAdd(&g_cnt[b * NI + l],
                  tab[0][l * PITCH + 32] + tab[1][l * PITCH + 32]);
    }
}

// ---------------------------------------------------------------------------
// Pass 2: variance term (blocks 0..31 per batch, 8192 px each) + distance and
// regularizer terms (block 32). Means table pitch 36 -> float4 LDS gathers.
__global__ void __launch_bounds__(1024) k_var(const float* __restrict__ in,
                                              const int* __restrict__ tgt,
                                              float* __restrict__ out) {
    __shared__ __align__(16) float sm[NI * P2];   // 14.4 KB
    __shared__ float red[32];

    const int b = blockIdx.y;
    if (threadIdx.x < NI) {
        const int l = threadIdx.x;
        const float inv = 1.0f / g_cnt[b * NI + l];
#pragma unroll
        for (int c = 0; c < CC; ++c)
            sm[l * P2 + c] = g_sum[(b * NI + l) * CC + c] * inv;
        sm[l * P2 + 32] = inv;
    }
    __syncthreads();

    float acc = 0.0f;
    if (blockIdx.x < 32) {
        const float* inb = in  + (size_t)b * CC * HW;
        const int*   tb  = tgt + (size_t)b * HW;
        const int p0 = blockIdx.x * 8192 + threadIdx.x;
#pragma unroll
        for (int k = 0; k < 8; ++k) {
            const int p = p0 + k * 1024;
            const int l = tb[p];
            const float4* m4 = (const float4*)(sm + l * P2);
            float d2 = 0.0f;
#pragma unroll
            for (int q = 0; q < 8; ++q) {
                const float4 mm = m4[q];
                const float vx = inb[(size_t)(4 * q + 0) * HW + p] - mm.x;
                const float vy = inb[(size_t)(4 * q + 1) * HW + p] - mm.y;
                const float vz = inb[(size_t)(4 * q + 2) * HW + p] - mm.z;
                const float vw = inb[(size_t)(4 * q + 3) * HW + p] - mm.w;
                d2 = fmaf(vx, vx, d2); d2 = fmaf(vy, vy, d2);
                d2 = fmaf(vz, vz, d2); d2 = fmaf(vw, vw, d2);
            }
            const float r = sqrtf(d2);
            const float h = fmaxf(r - DVAR, 0.0f);
            acc = fmaf(h * h, sm[l * P2 + 32], acc);
        }
        acc *= (1.0f / (NI * BB));                          // ALPHA = 1
    } else {
        float accd = 0.0f, accr = 0.0f;
        for (int idx = threadIdx.x; idx < NI * NI; idx += 1024) {
            const int i = idx / NI, j = idx - i * NI;
            if (i == j) continue;
            float d2 = 0.0f;
#pragma unroll
            for (int q = 0; q < 8; ++q) {
                const float4 a = *(const float4*)(sm + i * P2 + 4 * q);
                const float4 c = *(const float4*)(sm + j * P2 + 4 * q);
                const float vx = a.x - c.x, vy = a.y - c.y;
                const float vz = a.z - c.z, vw = a.w - c.w;
                d2 = fmaf(vx, vx, d2); d2 = fmaf(vy, vy, d2);
                d2 = fmaf(vz, vz, d2); d2 = fmaf(vw, vw, d2);
            }
            const float d = (d2 > 0.0f) ? sqrtf(d2) : 1.0f;
            const float h = fmaxf(REP - d, 0.0f);
            accd = fmaf(h, h, accd);
        }
        if (threadIdx.x < NI) {
            const int i = threadIdx.x;
            float n2 = 0.0f;
#pragma unroll
            for (int q = 0; q < 8; ++q) {
                const float4 a = *(const float4*)(sm + i * P2 + 4 * q);
                n2 = fmaf(a.x, a.x, n2); n2 = fmaf(a.y, a.y, n2);
                n2 = fmaf(a.z, a.z, n2); n2 = fmaf(a.w, a.w, n2);
            }
            accr = sqrtf(n2);
        }
        acc = accd * (1.0f / (NI * (NI - 1) * BB))          // BETA = 1
            + accr * (0.001f / (NI * BB));                  // GAMMA = 0.001
    }

#pragma unroll
    for (int o = 16; o > 0; o >>= 1) acc += __shfl_down_sync(0xffffffffu, acc, o);
    if ((threadIdx.x & 31) == 0) red[threadIdx.x >> 5] = acc;
    __syncthreads();
    if (threadIdx.x < 32) {
        float v = red[threadIdx.x];
#pragma unroll
        for (int o = 16; o > 0; o >>= 1) v += __shfl_down_sync(0xffffffffu, v, o);
        if (threadIdx.x == 0) atomicAdd(out, v);
    }
}

// ---------------------------------------------------------------------------
extern "C" void kernel_launch(void* const* d_in, const int* in_sizes, int n_in,
                              void* d_out, int out_size) {
    const float* in  = (const float*)d_in[0];
    const int*   tgt = (const int*)d_in[1];
    float* out = (float*)d_out;

    k_zero<<<52, 256>>>(out);
    dim3 g1(256, BB);
    k_pass1<<<g1, 64>>>(in, tgt);
    dim3 g2(33, BB);
    k_var<<<g2, 1024>>>(in, tgt, out);
}